// round 5
// baseline (speedup 1.0000x reference)
#include <cuda_runtime.h>

// ContinuousCRF, fused persistent kernel with low-latency wavefront sync.
// 96 CTAs (one image row each), 384 threads. Stencil mapping: 4 adjacent
// lanes per pixel (sub = tid&3 takes a compile-time quarter of the 80 disk
// taps), reduced with shfl_xor — no smem partials. Sync: per-row monotonic
// flags; each halo-loading thread polls (ld.acquire.gpu) only the rows it
// loads, then loads; publisher uses a single st.release.gpu after one
// __syncthreads. Own row is kept in smem (written by the epilogue), zero
// padding written once. 2 __syncthreads per iteration.

#define HH 96
#define WW 96
#define NPIX (HH * WW)
#define HALO 5
#define TW (WW + 2 * HALO)     // 106 smem cols
#define SROWS (1 + 2 * HALO)   // 11 smem rows
#define NBLK HH
#define TPB (WW * 4)           // 384
#define WLUT 121
#define NITER 5
#define TAPS_PER_GROUP 20
#define FLAG_STRIDE 32         // one 128B line per row flag

__device__ float4 g_q[2][NPIX];
__device__ unsigned g_done[HH * FLAG_STRIDE];   // monotonic per-row progress

__device__ __forceinline__ unsigned ld_acq(const unsigned* p)
{
    unsigned v;
    asm volatile("ld.acquire.gpu.global.u32 %0, [%1];" : "=r"(v) : "l"(p));
    return v;
}
__device__ __forceinline__ unsigned ld_cg_u32(const unsigned* p)
{
    unsigned v;
    asm volatile("ld.global.cg.u32 %0, [%1];" : "=r"(v) : "l"(p));
    return v;
}
__device__ __forceinline__ void st_rel(unsigned* p, unsigned v)
{
    asm volatile("st.release.gpu.global.u32 [%0], %1;" :: "l"(p), "r"(v) : "memory");
}
__device__ __forceinline__ float4 ld_cg_f4(const float4* p)
{
    float4 v;
    asm volatile("ld.global.cg.v4.f32 {%0,%1,%2,%3}, [%4];"
                 : "=f"(v.x), "=f"(v.y), "=f"(v.z), "=f"(v.w) : "l"(p));
    return v;
}
__device__ __forceinline__ void st_cg_f4(float4* p, float4 v)
{
    asm volatile("st.global.cg.v4.f32 [%0], {%1,%2,%3,%4};"
                 :: "l"(p), "f"(v.x), "f"(v.y), "f"(v.z), "f"(v.w) : "memory");
}

// Accumulate taps [G*20, G*20+20) of the 80 valid (dy,dx) disk offsets.
// t resolves at compile time after full unroll: exactly 20 LDS.128 + 60 FMA.
template <int G>
__device__ __forceinline__ void accum(const float4* __restrict__ s_q,
                                      const float*  __restrict__ s_w,
                                      int center,
                                      float& m0, float& m1, float& m2)
{
    int t = 0;
#pragma unroll
    for (int dy = -5; dy <= 5; dy++) {
#pragma unroll
        for (int dx = -5; dx <= 5; dx++) {
            const int d2 = dy * dy + dx * dx;
            if (d2 == 0 || d2 > 25) continue;
            if (t >= G * TAPS_PER_GROUP && t < (G + 1) * TAPS_PER_GROUP) {
                const float  w = s_w[(dy + 5) * 11 + (dx + 5)];
                const float4 v = s_q[center + dy * TW + dx];
                m0 = fmaf(w, v.x, m0);
                m1 = fmaf(w, v.y, m1);
                m2 = fmaf(w, v.z, m2);
            }
            t++;
        }
    }
}

__global__ __launch_bounds__(TPB, 1)
void crf_all(const float* __restrict__ unary,
             const float* __restrict__ comp,
             float* __restrict__ out)
{
    __shared__ float4 s_q[SROWS * TW];
    __shared__ float  s_w[WLUT];

    const int tid = threadIdx.x;
    const int y   = blockIdx.x;

    // stencil mapping: 4 adjacent lanes per pixel
    const int sub = tid & 3;
    const int px  = tid >> 2;          // 0..95
    const int n   = y * WW + px;

    // halo mapping
    const int hx  = tid % WW;          // 0..95
    const int hty = tid / WW;          // 0..3

    // Per-replay base of the monotonic counters (own flag; we're its only writer).
    const unsigned base = ld_cg_u32(&g_done[y * FLAG_STRIDE]);

    if (tid < WLUT) {
        const int dy = tid / 11 - 5;
        const int dx = tid % 11 - 5;
        const int d2 = dy * dy + dx * dx;
        s_w[tid] = (d2 > 0 && d2 <= 25) ? expf(-sqrtf((float)d2)) : 0.f;
    }

    const float c00 = __ldg(comp + 0), c01 = __ldg(comp + 1), c02 = __ldg(comp + 2);
    const float c10 = __ldg(comp + 3), c11 = __ldg(comp + 4), c12 = __ldg(comp + 5);
    const float c20 = __ldg(comp + 6), c21 = __ldg(comp + 7), c22 = __ldg(comp + 8);

    // Own pixel's unary logits (kept in registers across all iterations).
    const float u0 = __ldg(unary + n);
    const float u1 = __ldg(unary + NPIX + n);
    const float u2 = __ldg(unary + 2 * NPIX + n);

    // ---- iteration 0 tile fill: whole padded tile, q0 = softmax(unary) ----
    for (int i = tid; i < SROWS * TW; i += TPB) {
        const int r  = i / TW;
        const int cc = i - r * TW;
        const int gy = y - HALO + r;
        const int gx = cc - HALO;
        float4 v = make_float4(0.f, 0.f, 0.f, 0.f);
        if (gy >= 0 && gy < HH && gx >= 0 && gx < WW) {
            const int m = gy * WW + gx;
            const float a0 = __ldg(unary + m);
            const float a1 = __ldg(unary + NPIX + m);
            const float a2 = __ldg(unary + 2 * NPIX + m);
            const float mx = fmaxf(a0, fmaxf(a1, a2));
            const float e0 = expf(a0 - mx), e1 = expf(a1 - mx), e2 = expf(a2 - mx);
            const float rs = 1.f / (e0 + e1 + e2);
            v = make_float4(e0 * rs, e1 * rs, e2 * rs, 0.f);
        }
        s_q[i] = v;
    }

    const int center = HALO * TW + HALO + px;

    for (int it = 0; it < NITER; it++) {
        // ---- halo refresh (it>0): poll the source row's flag, then load.
        // Zero pad rows/cols and own row (r==5) are never reloaded. ----
        if (it > 0) {
            const float4* __restrict__ qsrc = g_q[(it + 1) & 1];
            const unsigned need = base + (unsigned)it;
#pragma unroll
            for (int k = 0; k < 3; k++) {
                const int r = hty + 4 * k;           // covers 0..10 \ {5} (+11 skipped)
                if (r < SROWS && r != HALO) {
                    const int gy = y - HALO + r;
                    if (gy >= 0 && gy < HH) {
                        const unsigned* f = &g_done[gy * FLAG_STRIDE];
                        while (ld_acq(f) < need) { }
                        s_q[r * TW + HALO + hx] = ld_cg_f4(qsrc + gy * WW + hx);
                    }
                }
            }
        }
        __syncthreads();   // (B) tile complete before stencil reads

        // ---- 80-tap stencil: quarter per sub-lane ----
        float m0 = 0.f, m1 = 0.f, m2 = 0.f;
        switch (sub) {
            case 0: accum<0>(s_q, s_w, center, m0, m1, m2); break;
            case 1: accum<1>(s_q, s_w, center, m0, m1, m2); break;
            case 2: accum<2>(s_q, s_w, center, m0, m1, m2); break;
            default: accum<3>(s_q, s_w, center, m0, m1, m2); break;
        }
        // reduce across the 4 sub-lanes (all lanes end with the total)
        m0 += __shfl_xor_sync(0xffffffffu, m0, 1);
        m0 += __shfl_xor_sync(0xffffffffu, m0, 2);
        m1 += __shfl_xor_sync(0xffffffffu, m1, 1);
        m1 += __shfl_xor_sync(0xffffffffu, m1, 2);
        m2 += __shfl_xor_sync(0xffffffffu, m2, 1);
        m2 += __shfl_xor_sync(0xffffffffu, m2, 2);

        // compat mix + softmax (computed redundantly on all 4 lanes)
        const float cm0 = c00 * m0 + c01 * m1 + c02 * m2;
        const float cm1 = c10 * m0 + c11 * m1 + c12 * m2;
        const float cm2 = c20 * m0 + c21 * m1 + c22 * m2;
        const float l0 = u0 + cm0, l1 = u1 + cm1, l2 = u2 + cm2;
        const float mx = fmaxf(l0, fmaxf(l1, l2));
        float e0 = expf(l0 - mx), e1 = expf(l1 - mx), e2 = expf(l2 - mx);
        const float rs = 1.f / (e0 + e1 + e2);
        e0 *= rs; e1 *= rs; e2 *= rs;

        if (it == NITER - 1) {
            // final: write planes in parallel (one channel per sub-lane)
            if (sub == 0)      out[n]            = e0;
            else if (sub == 1) out[NPIX + n]     = e1;
            else if (sub == 2) out[2 * NPIX + n] = e2;
        } else {
            if (sub == 0) st_cg_f4(&g_q[it & 1][n], make_float4(e0, e1, e2, 0.f));
            __syncthreads();   // (C) all q stores done + WAR on s_q reads
            // own row goes straight back into smem for the next iteration
            if (sub == 0) s_q[center] = make_float4(e0, e1, e2, 0.f);
            if (tid == 0) st_rel(&g_done[y * FLAG_STRIDE], base + (unsigned)(it + 1));
        }
    }
}

extern "C" void kernel_launch(void* const* d_in, const int* in_sizes, int n_in,
                              void* d_out, int out_size)
{
    (void)in_sizes; (void)n_in; (void)out_size;
    const float* unary = (const float*)d_in[0];
    const float* comp  = (const float*)d_in[1];
    float* out = (float*)d_out;

    crf_all<<<NBLK, TPB>>>(unary, comp, out);
}

// round 6
// speedup vs baseline: 1.0860x; 1.0860x over previous
#include <cuda_runtime.h>

// ContinuousCRF, fused persistent kernel, wavefront sync, divergence-free
// stencil. 96 CTAs (one image row each), 384 threads = 4 lanes/pixel; each
// lane's 20-tap quarter of the 80-tap radius-5 disk stencil lives in
// REGISTERS (offset+weight pairs hoisted at init), so the per-iteration
// stencil loop is uniform across the warp; partials reduced with shfl_xor.
// Sync: per-row monotonic flags; warp w polls+loads exactly one halo row.

#define HH 96
#define WW 96
#define NPIX (HH * WW)
#define HALO 5
#define TW (WW + 2 * HALO)     // 106 smem cols
#define SROWS (1 + 2 * HALO)   // 11 smem rows
#define NBLK HH
#define TPB 384
#define NITER 5
#define TPG 20                 // taps per group (80 / 4)
#define FLAG_STRIDE 32         // one 128B line per row flag

__device__ float4 g_q[2][NPIX];
__device__ unsigned g_done[HH * FLAG_STRIDE];   // monotonic per-row progress

__device__ __forceinline__ unsigned ld_cg_u32(const unsigned* p)
{
    unsigned v;
    asm volatile("ld.global.cg.u32 %0, [%1];" : "=r"(v) : "l"(p));
    return v;
}
__device__ __forceinline__ void st_rel(unsigned* p, unsigned v)
{
    asm volatile("st.release.gpu.global.u32 [%0], %1;" :: "l"(p), "r"(v) : "memory");
}
__device__ __forceinline__ void fence_acq()
{
    asm volatile("fence.acq_rel.gpu;" ::: "memory");
}
__device__ __forceinline__ float4 ld_cg_f4(const float4* p)
{
    float4 v;
    asm volatile("ld.global.cg.v4.f32 {%0,%1,%2,%3}, [%4];"
                 : "=f"(v.x), "=f"(v.y), "=f"(v.z), "=f"(v.w) : "l"(p));
    return v;
}
__device__ __forceinline__ void st_cg_f4(float4* p, float4 v)
{
    asm volatile("st.global.cg.v4.f32 [%0], {%1,%2,%3,%4};"
                 :: "l"(p), "f"(v.x), "f"(v.y), "f"(v.z), "f"(v.w) : "memory");
}

// Hoist taps [G*20, G*20+20) of the 80 valid (dy,dx) disk offsets into
// registers. t and c resolve at compile time after full unroll, so off[]/wt[]
// are indexed by constants -> stay in registers (no local-memory spill).
template <int G>
__device__ __forceinline__ void fill_taps(int* off, float* wt)
{
    int t = 0, c = 0;
#pragma unroll
    for (int dy = -5; dy <= 5; dy++) {
#pragma unroll
        for (int dx = -5; dx <= 5; dx++) {
            const int d2 = dy * dy + dx * dx;
            if (d2 == 0 || d2 > 25) continue;
            if (t >= G * TPG && t < (G + 1) * TPG) {
                off[c] = dy * TW + dx;
                wt[c]  = expf(-sqrtf((float)d2));
                c++;
            }
            t++;
        }
    }
}

__global__ __launch_bounds__(TPB, 1)
void crf_all(const float* __restrict__ unary,
             const float* __restrict__ comp,
             float* __restrict__ out)
{
    __shared__ float4 s_q[SROWS * TW];

    const int tid  = threadIdx.x;
    const int y    = blockIdx.x;
    const int sub  = tid & 3;          // tap quarter (4 adjacent lanes/pixel)
    const int px   = tid >> 2;         // 0..95
    const int n    = y * WW + px;
    const int wid  = tid >> 5;         // 0..11
    const int lane = tid & 31;

    // Per-replay base of the monotonic counters (own flag; we're its only writer).
    const unsigned base = ld_cg_u32(&g_done[y * FLAG_STRIDE]);

    // Tap set for this lane, in registers (divergent once, at init only).
    int off[TPG]; float wt[TPG];
    switch (sub) {
        case 0:  fill_taps<0>(off, wt); break;
        case 1:  fill_taps<1>(off, wt); break;
        case 2:  fill_taps<2>(off, wt); break;
        default: fill_taps<3>(off, wt); break;
    }

    const float c00 = __ldg(comp + 0), c01 = __ldg(comp + 1), c02 = __ldg(comp + 2);
    const float c10 = __ldg(comp + 3), c11 = __ldg(comp + 4), c12 = __ldg(comp + 5);
    const float c20 = __ldg(comp + 6), c21 = __ldg(comp + 7), c22 = __ldg(comp + 8);

    // Own pixel's unary logits (registers, all iterations).
    const float u0 = __ldg(unary + n);
    const float u1 = __ldg(unary + NPIX + n);
    const float u2 = __ldg(unary + 2 * NPIX + n);

    // ---- init tile fill: q0 = softmax(unary); zero pad written ONCE ----
    for (int i = tid; i < SROWS * TW; i += TPB) {
        const int r  = i / TW;
        const int cc = i - r * TW;
        const int gy = y - HALO + r;
        const int gx = cc - HALO;
        float4 v = make_float4(0.f, 0.f, 0.f, 0.f);
        if (gy >= 0 && gy < HH && gx >= 0 && gx < WW) {
            const int m = gy * WW + gx;
            const float a0 = __ldg(unary + m);
            const float a1 = __ldg(unary + NPIX + m);
            const float a2 = __ldg(unary + 2 * NPIX + m);
            const float mx = fmaxf(a0, fmaxf(a1, a2));
            const float e0 = expf(a0 - mx), e1 = expf(a1 - mx), e2 = expf(a2 - mx);
            const float rs = 1.f / (e0 + e1 + e2);
            v = make_float4(e0 * rs, e1 * rs, e2 * rs, 0.f);
        }
        s_q[i] = v;
    }

    const int center = HALO * TW + HALO + px;

    // Warp -> halo row assignment: warps 0..9 own rows 0..4, 6..10.
    const int  hr     = (wid < 5) ? wid : wid + 1;
    const int  hgy    = y - HALO + hr;
    const bool hvalid = (wid < 10) && (hgy >= 0) && (hgy < HH);

    for (int it = 0; it < NITER; it++) {
        // ---- halo refresh (it>0): one warp per source row; lane 0 polls
        // that row's flag, then the warp loads its 96 float4s. ----
        if (it > 0 && hvalid) {
            if (lane == 0) {
                const unsigned need = base + (unsigned)it;
                const unsigned* f = &g_done[hgy * FLAG_STRIDE];
                while (ld_cg_u32(f) < need) { __nanosleep(20); }
                fence_acq();
            }
            __syncwarp();
            const float4* __restrict__ src = g_q[(it + 1) & 1] + hgy * WW;
            float4* dst = &s_q[hr * TW + HALO];
            dst[lane]      = ld_cg_f4(src + lane);
            dst[lane + 32] = ld_cg_f4(src + lane + 32);
            dst[lane + 64] = ld_cg_f4(src + lane + 64);
        }
        __syncthreads();   // (A) tile complete before stencil reads

        // ---- 20-tap quarter stencil, uniform across the warp ----
        float m0 = 0.f, m1 = 0.f, m2 = 0.f;
#pragma unroll
        for (int k = 0; k < TPG; k++) {
            const float4 v = s_q[center + off[k]];
            m0 = fmaf(wt[k], v.x, m0);
            m1 = fmaf(wt[k], v.y, m1);
            m2 = fmaf(wt[k], v.z, m2);
        }
        // reduce across the 4 sub-lanes of this pixel
        m0 += __shfl_xor_sync(0xffffffffu, m0, 1);
        m0 += __shfl_xor_sync(0xffffffffu, m0, 2);
        m1 += __shfl_xor_sync(0xffffffffu, m1, 1);
        m1 += __shfl_xor_sync(0xffffffffu, m1, 2);
        m2 += __shfl_xor_sync(0xffffffffu, m2, 1);
        m2 += __shfl_xor_sync(0xffffffffu, m2, 2);

        // compat mix + softmax (redundant on the 4 lanes; cheap)
        const float cm0 = c00 * m0 + c01 * m1 + c02 * m2;
        const float cm1 = c10 * m0 + c11 * m1 + c12 * m2;
        const float cm2 = c20 * m0 + c21 * m1 + c22 * m2;
        const float l0 = u0 + cm0, l1 = u1 + cm1, l2 = u2 + cm2;
        const float mx = fmaxf(l0, fmaxf(l1, l2));
        float e0 = expf(l0 - mx), e1 = expf(l1 - mx), e2 = expf(l2 - mx);
        const float rs = 1.f / (e0 + e1 + e2);
        e0 *= rs; e1 *= rs; e2 *= rs;

        if (it == NITER - 1) {
            // channel-parallel final store (one plane per sub-lane)
            if (sub == 0)      out[n]            = e0;
            else if (sub == 1) out[NPIX + n]     = e1;
            else if (sub == 2) out[2 * NPIX + n] = e2;
        } else {
            if (sub == 0) st_cg_f4(&g_q[it & 1][n], make_float4(e0, e1, e2, 0.f));
            __syncthreads();   // (B) WAR: all stencil reads of s_q done
            if (sub == 0) s_q[center] = make_float4(e0, e1, e2, 0.f);  // own row stays local
            if (tid == 0) st_rel(&g_done[y * FLAG_STRIDE], base + (unsigned)(it + 1));
        }
    }
}

extern "C" void kernel_launch(void* const* d_in, const int* in_sizes, int n_in,
                              void* d_out, int out_size)
{
    (void)in_sizes; (void)n_in; (void)out_size;
    const float* unary = (const float*)d_in[0];
    const float* comp  = (const float*)d_in[1];
    float* out = (float*)d_out;

    crf_all<<<NBLK, TPB>>>(unary, comp, out);
}

// round 10
// speedup vs baseline: 1.0976x; 1.0107x over previous
#include <cuda_runtime.h>

// ContinuousCRF, fused persistent kernel, wavefront sync via tag-in-data
// carried in MORALLY-STRONG 128-bit accesses: q stored as (q0,q1,q2,TAG)
// with st.release.gpu.global.b128; consumers poll their halo pixels with
// ld.acquire.gpu.global.b128. 16B release/acquire is single-copy atomic and
// ordered (sm_90+), so tag and payload are indivisible — fixes R7's
// per-element visibility tear. No flags, no fences, per-pixel granularity.
// 96 CTAs (one row each), 384 threads = 4 lanes/pixel, 20 register-hoisted
// taps per lane, shfl_xor reduction, 2 __syncthreads per iteration.

#define HH 96
#define WW 96
#define NPIX (HH * WW)
#define HALO 5
#define TW (WW + 2 * HALO)     // 106 smem cols
#define SROWS (1 + 2 * HALO)   // 11 smem rows
#define NBLK HH
#define TPB 384
#define NITER 5
#define TPG 20                 // taps per group (80 / 4)

__device__ float4 g_q[2][NPIX];   // payload (q0,q1,q2) + tag in .w

// ---- strong 128-bit accesses (single-copy atomic + ordered) ----
__device__ __forceinline__ float4 ld_acq_f4(const float4* p)
{
    float4 v;
    asm volatile("{\n\t"
                 ".reg .b128 rr;\n\t"
                 "ld.acquire.gpu.global.b128 rr, [%4];\n\t"
                 "mov.b128 {%0, %1, %2, %3}, rr;\n\t"
                 "}"
                 : "=f"(v.x), "=f"(v.y), "=f"(v.z), "=f"(v.w) : "l"(p));
    return v;
}
__device__ __forceinline__ void st_rel_f4(float4* p, float4 v)
{
    asm volatile("{\n\t"
                 ".reg .b128 rr;\n\t"
                 "mov.b128 rr, {%1, %2, %3, %4};\n\t"
                 "st.release.gpu.global.b128 [%0], rr;\n\t"
                 "}"
                 :: "l"(p), "f"(v.x), "f"(v.y), "f"(v.z), "f"(v.w) : "memory");
}
__device__ __forceinline__ float4 ld_cg_f4(const float4* p)
{
    float4 v;
    asm volatile("ld.global.cg.v4.f32 {%0,%1,%2,%3}, [%4];"
                 : "=f"(v.x), "=f"(v.y), "=f"(v.z), "=f"(v.w) : "l"(p));
    return v;
}

// Hoist taps [G*20, G*20+20) of the 80 valid (dy,dx) disk offsets into
// registers (compile-time indices -> no local-memory spill).
template <int G>
__device__ __forceinline__ void fill_taps(int* off, float* wt)
{
    int t = 0, c = 0;
#pragma unroll
    for (int dy = -5; dy <= 5; dy++) {
#pragma unroll
        for (int dx = -5; dx <= 5; dx++) {
            const int d2 = dy * dy + dx * dx;
            if (d2 == 0 || d2 > 25) continue;
            if (t >= G * TPG && t < (G + 1) * TPG) {
                off[c] = dy * TW + dx;
                wt[c]  = expf(-sqrtf((float)d2));
                c++;
            }
            t++;
        }
    }
}

__global__ __launch_bounds__(TPB, 1)
void crf_all(const float* __restrict__ unary,
             const float* __restrict__ comp,
             float* __restrict__ out)
{
    __shared__ float4 s_q[SROWS * TW];

    const int tid  = threadIdx.x;
    const int y    = blockIdx.x;
    const int sub  = tid & 3;          // tap quarter (4 adjacent lanes/pixel)
    const int px   = tid >> 2;         // 0..95
    const int n    = y * WW + px;
    const int wid  = tid >> 5;         // 0..11
    const int lane = tid & 31;

    // Monotonic tag base: our row's last write of the previous replay left
    // tag = base_prev + 4 in g_q[1]. Zero-init globals give 0 on first run.
    // We are the only writer of our row, so this read is race-free.
    const float base = ld_cg_f4(&g_q[1][y * WW]).w;

    // Tap set for this lane, in registers (divergent once, init only).
    int off[TPG]; float wt[TPG];
    switch (sub) {
        case 0:  fill_taps<0>(off, wt); break;
        case 1:  fill_taps<1>(off, wt); break;
        case 2:  fill_taps<2>(off, wt); break;
        default: fill_taps<3>(off, wt); break;
    }

    const float c00 = __ldg(comp + 0), c01 = __ldg(comp + 1), c02 = __ldg(comp + 2);
    const float c10 = __ldg(comp + 3), c11 = __ldg(comp + 4), c12 = __ldg(comp + 5);
    const float c20 = __ldg(comp + 6), c21 = __ldg(comp + 7), c22 = __ldg(comp + 8);

    // Own pixel's unary logits (registers, all iterations).
    const float u0 = __ldg(unary + n);
    const float u1 = __ldg(unary + NPIX + n);
    const float u2 = __ldg(unary + 2 * NPIX + n);

    // ---- init tile fill: q0 = softmax(unary); zero pad written ONCE ----
    for (int i = tid; i < SROWS * TW; i += TPB) {
        const int r  = i / TW;
        const int cc = i - r * TW;
        const int gy = y - HALO + r;
        const int gx = cc - HALO;
        float4 v = make_float4(0.f, 0.f, 0.f, 0.f);
        if (gy >= 0 && gy < HH && gx >= 0 && gx < WW) {
            const int m = gy * WW + gx;
            const float a0 = __ldg(unary + m);
            const float a1 = __ldg(unary + NPIX + m);
            const float a2 = __ldg(unary + 2 * NPIX + m);
            const float mx = fmaxf(a0, fmaxf(a1, a2));
            const float e0 = expf(a0 - mx), e1 = expf(a1 - mx), e2 = expf(a2 - mx);
            const float rs = 1.f / (e0 + e1 + e2);
            v = make_float4(e0 * rs, e1 * rs, e2 * rs, 0.f);
        }
        s_q[i] = v;
    }

    const int center = HALO * TW + HALO + px;

    // Warp -> halo row assignment: warps 0..9 own rows 0..4, 6..10.
    const int  hr     = (wid < 5) ? wid : wid + 1;
    const int  hgy    = y - HALO + hr;
    const bool hvalid = (wid < 10) && (hgy >= 0) && (hgy < HH);

    for (int it = 0; it < NITER; it++) {
        // ---- halo refresh (it>0): acquire-poll the neighbor pixels' tags.
        // Data written at iteration it-1 carries tag base + it. ----
        if (it > 0 && hvalid) {
            const float tag = base + (float)it;
            const float4* __restrict__ src = g_q[(it + 1) & 1] + hgy * WW;
            float4 a = ld_acq_f4(src + lane);
            float4 b = ld_acq_f4(src + lane + 32);
            float4 c = ld_acq_f4(src + lane + 64);
            while (a.w != tag) a = ld_acq_f4(src + lane);
            while (b.w != tag) b = ld_acq_f4(src + lane + 32);
            while (c.w != tag) c = ld_acq_f4(src + lane + 64);
            float4* dst = &s_q[hr * TW + HALO];
            dst[lane]      = a;
            dst[lane + 32] = b;
            dst[lane + 64] = c;
        }
        __syncthreads();   // (A) tile complete before stencil reads

        // ---- 20-tap quarter stencil, uniform across the warp ----
        float m0 = 0.f, m1 = 0.f, m2 = 0.f;
#pragma unroll
        for (int k = 0; k < TPG; k++) {
            const float4 v = s_q[center + off[k]];
            m0 = fmaf(wt[k], v.x, m0);
            m1 = fmaf(wt[k], v.y, m1);
            m2 = fmaf(wt[k], v.z, m2);
        }
        // reduce across the 4 sub-lanes of this pixel
        m0 += __shfl_xor_sync(0xffffffffu, m0, 1);
        m0 += __shfl_xor_sync(0xffffffffu, m0, 2);
        m1 += __shfl_xor_sync(0xffffffffu, m1, 1);
        m1 += __shfl_xor_sync(0xffffffffu, m1, 2);
        m2 += __shfl_xor_sync(0xffffffffu, m2, 1);
        m2 += __shfl_xor_sync(0xffffffffu, m2, 2);

        // compat mix + softmax (redundant on the 4 lanes; cheap)
        const float cm0 = c00 * m0 + c01 * m1 + c02 * m2;
        const float cm1 = c10 * m0 + c11 * m1 + c12 * m2;
        const float cm2 = c20 * m0 + c21 * m1 + c22 * m2;
        const float l0 = u0 + cm0, l1 = u1 + cm1, l2 = u2 + cm2;
        const float mx = fmaxf(l0, fmaxf(l1, l2));
        float e0 = expf(l0 - mx), e1 = expf(l1 - mx), e2 = expf(l2 - mx);
        const float rs = 1.f / (e0 + e1 + e2);
        e0 *= rs; e1 *= rs; e2 *= rs;

        if (it == NITER - 1) {
            // channel-parallel final store (one plane per sub-lane)
            if (sub == 0)      out[n]            = e0;
            else if (sub == 1) out[NPIX + n]     = e1;
            else if (sub == 2) out[2 * NPIX + n] = e2;
        } else {
            // Publish payload+tag in ONE atomic, ordered 128-bit store.
            if (sub == 0)
                st_rel_f4(&g_q[it & 1][n],
                          make_float4(e0, e1, e2, base + (float)(it + 1)));
            __syncthreads();   // (B) WAR: all stencil reads of s_q done
            if (sub == 0) s_q[center] = make_float4(e0, e1, e2, 0.f);  // own row stays local
        }
    }
}

extern "C" void kernel_launch(void* const* d_in, const int* in_sizes, int n_in,
                              void* d_out, int out_size)
{
    (void)in_sizes; (void)n_in; (void)out_size;
    const float* unary = (const float*)d_in[0];
    const float* comp  = (const float*)d_in[1];
    float* out = (float*)d_out;

    crf_all<<<NBLK, TPB>>>(unary, comp, out);
}

// round 12
// speedup vs baseline: 1.3662x; 1.2448x over previous
#include <cuda_runtime.h>

// ContinuousCRF, fused persistent kernel, wavefront sync via tag-in-data in
// RELAXED single-copy-atomic 128-bit accesses (tag+payload share one 16B
// atom, so no acquire/release ordering is needed at all). Consumer polls all
// its halo pixels in ONE fused loop (concurrent reloads -> ~1 L2 round trip
// to detect). Double-buffered smem tile -> single __syncthreads/iteration.
// 96 CTAs (one row each), 384 threads = 4 lanes/pixel, 20 register-hoisted
// taps per lane, shfl_xor reduction.

#define HH 96
#define WW 96
#define NPIX (HH * WW)
#define HALO 5
#define TW (WW + 2 * HALO)     // 106 smem cols
#define SROWS (1 + 2 * HALO)   // 11 smem rows
#define NBLK HH
#define TPB 384
#define NITER 5
#define TPG 20                 // taps per group (80 / 4)

__device__ float4 g_q[2][NPIX];   // payload (q0,q1,q2) + tag in .w

// ---- relaxed 128-bit accesses (single-copy atomic, scope gpu) ----
__device__ __forceinline__ float4 ld_rlx_f4(const float4* p)
{
    float4 v;
    asm volatile("{\n\t"
                 ".reg .b128 rr;\n\t"
                 "ld.relaxed.gpu.global.b128 rr, [%4];\n\t"
                 "mov.b128 {%0, %1, %2, %3}, rr;\n\t"
                 "}"
                 : "=f"(v.x), "=f"(v.y), "=f"(v.z), "=f"(v.w) : "l"(p));
    return v;
}
__device__ __forceinline__ void st_rlx_f4(float4* p, float4 v)
{
    asm volatile("{\n\t"
                 ".reg .b128 rr;\n\t"
                 "mov.b128 rr, {%1, %2, %3, %4};\n\t"
                 "st.relaxed.gpu.global.b128 [%0], rr;\n\t"
                 "}"
                 :: "l"(p), "f"(v.x), "f"(v.y), "f"(v.z), "f"(v.w) : "memory");
}

// Hoist taps [G*20, G*20+20) of the 80 valid (dy,dx) disk offsets into
// registers (compile-time indices -> no local-memory spill).
template <int G>
__device__ __forceinline__ void fill_taps(int* off, float* wt)
{
    int t = 0, c = 0;
#pragma unroll
    for (int dy = -5; dy <= 5; dy++) {
#pragma unroll
        for (int dx = -5; dx <= 5; dx++) {
            const int d2 = dy * dy + dx * dx;
            if (d2 == 0 || d2 > 25) continue;
            if (t >= G * TPG && t < (G + 1) * TPG) {
                off[c] = dy * TW + dx;
                wt[c]  = expf(-sqrtf((float)d2));
                c++;
            }
            t++;
        }
    }
}

__global__ __launch_bounds__(TPB, 1)
void crf_all(const float* __restrict__ unary,
             const float* __restrict__ comp,
             float* __restrict__ out)
{
    __shared__ float4 s_q[2][SROWS * TW];   // double-buffered padded tile

    const int tid  = threadIdx.x;
    const int y    = blockIdx.x;
    const int sub  = tid & 3;          // tap quarter (4 adjacent lanes/pixel)
    const int px   = tid >> 2;         // 0..95
    const int n    = y * WW + px;
    const int wid  = tid >> 5;         // 0..11
    const int lane = tid & 31;

    // Monotonic tag base: our row's last write of the previous replay left
    // tag = base_prev + 4 in g_q[1]. Zero-init globals give 0 on first run.
    // We are the only writer of our row, so this read is race-free.
    const float base = ld_rlx_f4(&g_q[1][y * WW]).w;

    // Tap set for this lane, in registers (divergent once, init only).
    int off[TPG]; float wt[TPG];
    switch (sub) {
        case 0:  fill_taps<0>(off, wt); break;
        case 1:  fill_taps<1>(off, wt); break;
        case 2:  fill_taps<2>(off, wt); break;
        default: fill_taps<3>(off, wt); break;
    }

    const float c00 = __ldg(comp + 0), c01 = __ldg(comp + 1), c02 = __ldg(comp + 2);
    const float c10 = __ldg(comp + 3), c11 = __ldg(comp + 4), c12 = __ldg(comp + 5);
    const float c20 = __ldg(comp + 6), c21 = __ldg(comp + 7), c22 = __ldg(comp + 8);

    // Own pixel's unary logits (registers, all iterations).
    const float u0 = __ldg(unary + n);
    const float u1 = __ldg(unary + NPIX + n);
    const float u2 = __ldg(unary + 2 * NPIX + n);

    // ---- init: zero pad (BOTH tiles, written once); q0 = softmax(unary)
    // into tile 0's in-image cells ----
    for (int i = tid; i < SROWS * TW; i += TPB) {
        const int r  = i / TW;
        const int cc = i - r * TW;
        const int gy = y - HALO + r;
        const int gx = cc - HALO;
        if (gy >= 0 && gy < HH && gx >= 0 && gx < WW) {
            const int m = gy * WW + gx;
            const float a0 = __ldg(unary + m);
            const float a1 = __ldg(unary + NPIX + m);
            const float a2 = __ldg(unary + 2 * NPIX + m);
            const float mx = fmaxf(a0, fmaxf(a1, a2));
            const float e0 = expf(a0 - mx), e1 = expf(a1 - mx), e2 = expf(a2 - mx);
            const float rs = 1.f / (e0 + e1 + e2);
            s_q[0][i] = make_float4(e0 * rs, e1 * rs, e2 * rs, 0.f);
        } else {
            s_q[0][i] = make_float4(0.f, 0.f, 0.f, 0.f);
            s_q[1][i] = make_float4(0.f, 0.f, 0.f, 0.f);
        }
    }

    const int center = HALO * TW + HALO + px;

    // Warp -> halo row assignment: warps 0..9 own rows 0..4, 6..10.
    const int  hr     = (wid < 5) ? wid : wid + 1;
    const int  hgy    = y - HALO + hr;
    const bool hvalid = (wid < 10) && (hgy >= 0) && (hgy < HH);

    for (int it = 0; it < NITER; it++) {
        float4* __restrict__ tile = s_q[it & 1];

        // ---- halo refresh (it>0): fused concurrent tag-poll of the 3
        // pixels this lane owns in its halo row. Data written at iteration
        // it-1 carries tag base + it. ----
        if (it > 0 && hvalid) {
            const float tag = base + (float)it;
            const float4* __restrict__ src = g_q[(it + 1) & 1] + hgy * WW;
            float4 a = ld_rlx_f4(src + lane);
            float4 b = ld_rlx_f4(src + lane + 32);
            float4 c = ld_rlx_f4(src + lane + 64);
            while (a.w != tag || b.w != tag || c.w != tag) {
                if (a.w != tag) a = ld_rlx_f4(src + lane);
                if (b.w != tag) b = ld_rlx_f4(src + lane + 32);
                if (c.w != tag) c = ld_rlx_f4(src + lane + 64);
            }
            float4* dst = &tile[hr * TW + HALO];
            dst[lane]      = a;
            dst[lane + 32] = b;
            dst[lane + 64] = c;
        }
        __syncthreads();   // (A) tile complete before stencil reads

        // ---- 20-tap quarter stencil, uniform across the warp ----
        float m0 = 0.f, m1 = 0.f, m2 = 0.f;
#pragma unroll
        for (int k = 0; k < TPG; k++) {
            const float4 v = tile[center + off[k]];
            m0 = fmaf(wt[k], v.x, m0);
            m1 = fmaf(wt[k], v.y, m1);
            m2 = fmaf(wt[k], v.z, m2);
        }
        // reduce across the 4 sub-lanes of this pixel
        m0 += __shfl_xor_sync(0xffffffffu, m0, 1);
        m0 += __shfl_xor_sync(0xffffffffu, m0, 2);
        m1 += __shfl_xor_sync(0xffffffffu, m1, 1);
        m1 += __shfl_xor_sync(0xffffffffu, m1, 2);
        m2 += __shfl_xor_sync(0xffffffffu, m2, 1);
        m2 += __shfl_xor_sync(0xffffffffu, m2, 2);

        // compat mix + softmax (redundant on the 4 lanes; cheap)
        const float cm0 = c00 * m0 + c01 * m1 + c02 * m2;
        const float cm1 = c10 * m0 + c11 * m1 + c12 * m2;
        const float cm2 = c20 * m0 + c21 * m1 + c22 * m2;
        const float l0 = u0 + cm0, l1 = u1 + cm1, l2 = u2 + cm2;
        const float mx = fmaxf(l0, fmaxf(l1, l2));
        float e0 = expf(l0 - mx), e1 = expf(l1 - mx), e2 = expf(l2 - mx);
        const float rs = 1.f / (e0 + e1 + e2);
        e0 *= rs; e1 *= rs; e2 *= rs;

        if (it == NITER - 1) {
            // channel-parallel final store (one plane per sub-lane)
            if (sub == 0)      out[n]            = e0;
            else if (sub == 1) out[NPIX + n]     = e1;
            else if (sub == 2) out[2 * NPIX + n] = e2;
        } else {
            if (sub == 0) {
                // Publish payload+tag in ONE atomic 128-bit store (relaxed:
                // tag and payload share the atom, no ordering needed).
                st_rlx_f4(&g_q[it & 1][n],
                          make_float4(e0, e1, e2, base + (float)(it + 1)));
                // Own row goes straight into the NEXT tile (read only after
                // next iteration's bar (A), which orders it). No bar here.
                s_q[(it + 1) & 1][center] = make_float4(e0, e1, e2, 0.f);
            }
        }
    }
}

extern "C" void kernel_launch(void* const* d_in, const int* in_sizes, int n_in,
                              void* d_out, int out_size)
{
    (void)in_sizes; (void)n_in; (void)out_size;
    const float* unary = (const float*)d_in[0];
    const float* comp  = (const float*)d_in[1];
    float* out = (float*)d_out;

    crf_all<<<NBLK, TPB>>>(unary, comp, out);
}